// round 11
// baseline (speedup 1.0000x reference)
#include <cuda_runtime.h>
#include <cuda_bf16.h>
#include <math.h>

// ---------------------------------------------------------------------------
// MessageBlock, round 11:
//   K0: fused zero-output + node MLP (64x128 tile, 4m x 8n register tile ->
//       smem-BW per MAC halved; MLP goes from smem-bound ~56us to
//       FMA2-bound ~30us)
//   K1: edge kernel EXACTLY as the best (187.1us) round-2 version.
// ---------------------------------------------------------------------------

#define F_DIM   128
#define PHI_DIM 384
#define RBF_D   20
#define TILE_M  64
#define KC      16
#define EB      64   // edges per block

typedef unsigned long long ull;

// scratch for per-node phi (15.7 MB), static device allocation (allowed)
__device__ float g_phi[10240 * PHI_DIM];

__device__ __forceinline__ float decode_rc(const int* p) {
    int v = *p;
    if (v > 0 && v < 1000000) return (float)v;   // int32 scalar
    return __uint_as_float((unsigned)v);          // float32 scalar bits
}

// ---- packed f32x2 helpers (sm_103a FFMA2 path) -----------------------------
__device__ __forceinline__ ull pk2(float lo, float hi) {
    ull r; asm("mov.b64 %0, {%1, %2};" : "=l"(r) : "f"(lo), "f"(hi)); return r;
}
__device__ __forceinline__ ull fma2(ull a, ull b, ull c) {
    ull d; asm("fma.rn.f32x2 %0, %1, %2, %3;" : "=l"(d) : "l"(a), "l"(b), "l"(c));
    return d;
}
__device__ __forceinline__ float2 unpk2(ull p) {
    float2 v; asm("mov.b64 {%0, %1}, %2;" : "=f"(v.x), "=f"(v.y) : "l"(p));
    return v;
}

// ---------------------------------------------------------------------------
// K0: fused zero + node MLP.
// phi = (silu(s @ Ws1^T + bs1)) @ Ws2^T + bs2 -> g_phi [N,384]
// 256 threads, TILE_M=64. Thread grid: 16 n-groups (8 cols) x 16 m-groups
// (4 rows). B loads: 2 LDS.128 per (kk) serving 4m x 8n; A loads broadcast.
// ---------------------------------------------------------------------------
__global__ void __launch_bounds__(256) mlp_kernel(
    const float* __restrict__ s,
    const float* __restrict__ Ws1, const float* __restrict__ bs1,
    const float* __restrict__ Ws2, const float* __restrict__ bs2,
    int n_nodes,
    float* __restrict__ outp, int out_n)
{
    __shared__ __align__(16) float sh_sm[TILE_M][F_DIM];   // 32 KB: s, then h
    __shared__ __align__(16) float w_sm[KC][F_DIM + 4];    // 8.25 KB

    const int tid   = threadIdx.x;
    const int m_blk = blockIdx.x * TILE_M;
    const int n0 = (tid & 15) * 8;    // 16 n-groups of 8
    const int m0 = (tid >> 4) * 4;    // 16 m-groups of 4

    // ---- fused zero of the (poisoned) output ----
    {
        float4* o4 = (float4*)outp;
        const int n4 = out_n >> 2;           // out_n divisible by 4
        const int gtid = blockIdx.x * 256 + tid;
        const int gsz  = gridDim.x * 256;
        for (int i = gtid; i < n4; i += gsz)
            o4[i] = make_float4(0.f, 0.f, 0.f, 0.f);
    }

    // ---- stage s tile (zero-pad past n_nodes) ----
    for (int i = tid; i < TILE_M * 32; i += 256) {
        int m = i >> 5;
        float4 v = make_float4(0.f, 0.f, 0.f, 0.f);
        if (m_blk + m < n_nodes)
            v = ((const float4*)s)[(size_t)(m_blk + m) * 32 + (i & 31)];
        ((float4*)sh_sm)[i] = v;
    }

    ull accp[4][4];   // [m-sub][n-pair] : 4m x 8n in packed fp32 pairs

    // ---------------- stage 1: h = silu(s @ Ws1^T + bs1) ----------------
    #pragma unroll
    for (int i = 0; i < 4; i++)
        #pragma unroll
        for (int j = 0; j < 4; j++) accp[i][j] = 0ull;

    for (int kc = 0; kc < F_DIM; kc += KC) {
        __syncthreads();
        for (int i = tid; i < KC * F_DIM; i += 256) {
            int kk = i & (KC - 1);
            int n  = i >> 4;
            w_sm[kk][n] = Ws1[n * F_DIM + kc + kk];
        }
        __syncthreads();
        #pragma unroll
        for (int k4 = 0; k4 < KC; k4 += 4) {
            float a[4][4];
            #pragma unroll
            for (int i = 0; i < 4; i++) {
                float4 t = *(const float4*)&sh_sm[m0 + i][kc + k4];
                a[i][0] = t.x; a[i][1] = t.y; a[i][2] = t.z; a[i][3] = t.w;
            }
            #pragma unroll
            for (int kk = 0; kk < 4; kk++) {
                double2 bq0 = *(const double2*)&w_sm[k4 + kk][n0];
                double2 bq1 = *(const double2*)&w_sm[k4 + kk][n0 + 4];
                ull bA = __double_as_longlong(bq0.x);
                ull bB = __double_as_longlong(bq0.y);
                ull bC = __double_as_longlong(bq1.x);
                ull bD = __double_as_longlong(bq1.y);
                #pragma unroll
                for (int i = 0; i < 4; i++) {
                    ull aa = pk2(a[i][kk], a[i][kk]);
                    accp[i][0] = fma2(aa, bA, accp[i][0]);
                    accp[i][1] = fma2(aa, bB, accp[i][1]);
                    accp[i][2] = fma2(aa, bC, accp[i][2]);
                    accp[i][3] = fma2(aa, bD, accp[i][3]);
                }
            }
        }
    }

    // silu + bias -> overwrite sh_sm with h (after ALL s reads complete)
    __syncthreads();
    {
        float bb[8];
        #pragma unroll
        for (int j = 0; j < 8; j++) bb[j] = bs1[n0 + j];
        #pragma unroll
        for (int i = 0; i < 4; i++) {
            float h[8];
            #pragma unroll
            for (int j = 0; j < 4; j++) {
                float2 e = unpk2(accp[i][j]);
                float x0 = e.x + bb[2 * j];
                float x1 = e.y + bb[2 * j + 1];
                h[2 * j]     = x0 / (1.f + __expf(-x0));
                h[2 * j + 1] = x1 / (1.f + __expf(-x1));
            }
            *(float4*)&sh_sm[m0 + i][n0]     = make_float4(h[0], h[1], h[2], h[3]);
            *(float4*)&sh_sm[m0 + i][n0 + 4] = make_float4(h[4], h[5], h[6], h[7]);
        }
    }

    // ---------------- stage 2: phi = h @ Ws2^T + bs2 (3 passes of 128) --
    for (int p = 0; p < 3; p++) {
        #pragma unroll
        for (int i = 0; i < 4; i++)
            #pragma unroll
            for (int j = 0; j < 4; j++) accp[i][j] = 0ull;

        const float* W2 = Ws2 + (size_t)p * 128 * F_DIM;
        for (int kc = 0; kc < F_DIM; kc += KC) {
            __syncthreads();   // also orders h writes before first read
            for (int i = tid; i < KC * F_DIM; i += 256) {
                int kk = i & (KC - 1);
                int n  = i >> 4;
                w_sm[kk][n] = W2[n * F_DIM + kc + kk];
            }
            __syncthreads();
            #pragma unroll
            for (int k4 = 0; k4 < KC; k4 += 4) {
                float a[4][4];
                #pragma unroll
                for (int i = 0; i < 4; i++) {
                    float4 t = *(const float4*)&sh_sm[m0 + i][kc + k4];
                    a[i][0] = t.x; a[i][1] = t.y; a[i][2] = t.z; a[i][3] = t.w;
                }
                #pragma unroll
                for (int kk = 0; kk < 4; kk++) {
                    double2 bq0 = *(const double2*)&w_sm[k4 + kk][n0];
                    double2 bq1 = *(const double2*)&w_sm[k4 + kk][n0 + 4];
                    ull bA = __double_as_longlong(bq0.x);
                    ull bB = __double_as_longlong(bq0.y);
                    ull bC = __double_as_longlong(bq1.x);
                    ull bD = __double_as_longlong(bq1.y);
                    #pragma unroll
                    for (int i = 0; i < 4; i++) {
                        ull aa = pk2(a[i][kk], a[i][kk]);
                        accp[i][0] = fma2(aa, bA, accp[i][0]);
                        accp[i][1] = fma2(aa, bB, accp[i][1]);
                        accp[i][2] = fma2(aa, bC, accp[i][2]);
                        accp[i][3] = fma2(aa, bD, accp[i][3]);
                    }
                }
            }
        }
        float bb[8];
        #pragma unroll
        for (int j = 0; j < 8; j++) bb[j] = bs2[p * 128 + n0 + j];
        #pragma unroll
        for (int i = 0; i < 4; i++) {
            if (m_blk + m0 + i < n_nodes) {
                float o[8];
                #pragma unroll
                for (int j = 0; j < 4; j++) {
                    float2 e = unpk2(accp[i][j]);
                    o[2 * j]     = e.x + bb[2 * j];
                    o[2 * j + 1] = e.y + bb[2 * j + 1];
                }
                float* dst = &g_phi[(size_t)(m_blk + m0 + i) * PHI_DIM + p * 128 + n0];
                *(float4*)dst       = make_float4(o[0], o[1], o[2], o[3]);
                *(float4*)(dst + 4) = make_float4(o[4], o[5], o[6], o[7]);
            }
        }
    }
}

// ---------------------------------------------------------------------------
// K1: edge kernel — EXACT copy of the best (187.1us) round-2 version.
// 128 threads, thread t owns feature channels {t, t+128, t+256}.
// ---------------------------------------------------------------------------
__global__ void __launch_bounds__(128) edge_kernel(
    const float* __restrict__ vec,
    const float* __restrict__ edge_vector,
    const float* __restrict__ edge_distance,
    const float* __restrict__ edge_rbf,
    const float* __restrict__ Wrbf, const float* __restrict__ brbf,
    const int*   __restrict__ edge_idx,
    float* __restrict__ out_ds, float* __restrict__ out_dvec,
    int n_edges, const int* __restrict__ cutoff_ptr)
{
    __shared__ __align__(16) float rbf_sm[EB * RBF_D];   // 5 KB
    __shared__ float4 geo_sm[EB];                        // vn0,vn1,vn2,fcut
    __shared__ int2   idx_sm[EB];                        // (dst, src)

    const int tid = threadIdx.x;
    const float rc     = decode_rc(cutoff_ptr);
    const float inv_rc = 1.0f / rc;

    ull wp0[RBF_D / 2], wp1[RBF_D / 2], wp2[RBF_D / 2];
    #pragma unroll
    for (int q = 0; q < RBF_D / 2; q++) {
        wp0[q] = pk2(Wrbf[(tid      ) * RBF_D + 2 * q], Wrbf[(tid      ) * RBF_D + 2 * q + 1]);
        wp1[q] = pk2(Wrbf[(tid + 128) * RBF_D + 2 * q], Wrbf[(tid + 128) * RBF_D + 2 * q + 1]);
        wp2[q] = pk2(Wrbf[(tid + 256) * RBF_D + 2 * q], Wrbf[(tid + 256) * RBF_D + 2 * q + 1]);
    }
    const float b0 = brbf[tid], b1 = brbf[tid + 128], b2 = brbf[tid + 256];

    const int n_batches = (n_edges + EB - 1) / EB;
    for (int batch = blockIdx.x; batch < n_batches; batch += gridDim.x) {
        const int e0  = batch * EB;
        const int cnt = min(EB, n_edges - e0);

        __syncthreads();
        {
            const float4* src4 = (const float4*)(edge_rbf + (size_t)e0 * RBF_D);
            float4* dst4 = (float4*)rbf_sm;
            const int n4 = cnt * (RBF_D / 4);
            for (int i = tid; i < n4; i += 128) dst4[i] = src4[i];
        }
        if (tid < cnt) {
            const int e = e0 + tid;
            const float d = edge_distance[e];
            float fc = 0.5f * (cospif(d * inv_rc) + 1.0f);
            fc = (d < rc) ? fc : 0.0f;
            const float inv_d = 1.0f / d;
            geo_sm[tid] = make_float4(edge_vector[e * 3 + 0] * inv_d,
                                      edge_vector[e * 3 + 1] * inv_d,
                                      edge_vector[e * 3 + 2] * inv_d,
                                      fc);
            idx_sm[tid] = make_int2(edge_idx[e],              // dst (receiver)
                                    edge_idx[n_edges + e]);   // src (sender)
        }
        __syncthreads();

        #pragma unroll 1
        for (int el = 0; el < cnt; el++) {
            const int2  ii = idx_sm[el];
            const float4 g = geo_sm[el];
            const int dst = ii.x, src = ii.y;

            const double2* fp = (const double2*)(rbf_sm + el * RBF_D);
            ull acc0 = 0ull, acc1 = 0ull, acc2 = 0ull;
            #pragma unroll
            for (int q = 0; q < 5; q++) {
                double2 f = fp[q];
                ull fA = __double_as_longlong(f.x);
                ull fB = __double_as_longlong(f.y);
                acc0 = fma2(fA, wp0[2 * q], acc0);
                acc1 = fma2(fA, wp1[2 * q], acc1);
                acc2 = fma2(fA, wp2[2 * q], acc2);
                acc0 = fma2(fB, wp0[2 * q + 1], acc0);
                acc1 = fma2(fB, wp1[2 * q + 1], acc1);
                acc2 = fma2(fB, wp2[2 * q + 1], acc2);
            }
            float2 u0 = unpk2(acc0), u1 = unpk2(acc1), u2 = unpk2(acc2);
            const float fc = g.w;
            const float a0 = (u0.x + u0.y + b0) * fc;
            const float a1 = (u1.x + u1.y + b1) * fc;
            const float a2 = (u2.x + u2.y + b2) * fc;

            const float* ph = g_phi + (size_t)src * PHI_DIM;
            const float ws  = __ldg(ph + tid)       * a0;
            const float wvv = __ldg(ph + tid + 128) * a1;
            const float wvs = __ldg(ph + tid + 256) * a2;

            atomicAdd(out_ds + (size_t)dst * F_DIM + tid, ws);

            const float* vp = vec + (size_t)src * PHI_DIM;
            float* op = out_dvec + (size_t)dst * PHI_DIM + tid;
            atomicAdd(op,       fmaf(wvv, __ldg(vp + tid      ), g.x * wvs));
            atomicAdd(op + 128, fmaf(wvv, __ldg(vp + tid + 128), g.y * wvs));
            atomicAdd(op + 256, fmaf(wvv, __ldg(vp + tid + 256), g.z * wvs));
        }
    }
}

// ---------------------------------------------------------------------------
extern "C" void kernel_launch(void* const* d_in, const int* in_sizes, int n_in,
                              void* d_out, int out_size) {
    const float* s    = (const float*)d_in[0];
    const float* vec  = (const float*)d_in[1];
    const float* ev   = (const float*)d_in[2];
    const float* ed   = (const float*)d_in[3];
    const float* erbf = (const float*)d_in[4];
    const float* Ws1  = (const float*)d_in[5];
    const float* bs1  = (const float*)d_in[6];
    const float* Ws2  = (const float*)d_in[7];
    const float* bs2  = (const float*)d_in[8];
    const float* Wrbf = (const float*)d_in[9];
    const float* brbf = (const float*)d_in[10];
    const int*   eidx = (const int*)d_in[11];
    const int*   rcp  = (const int*)d_in[12];

    const int n_nodes = in_sizes[0] / F_DIM;
    const int n_edges = in_sizes[3];
    float* out_ds   = (float*)d_out;
    float* out_dvec = out_ds + (size_t)n_nodes * F_DIM;

    // K0: fused zero + per-node MLP -> g_phi
    mlp_kernel<<<(n_nodes + TILE_M - 1) / TILE_M, 256>>>(
        s, Ws1, bs1, Ws2, bs2, n_nodes, (float*)d_out, out_size);

    // K1: per-edge filter + scatter (exact 187us version)
    int nb = (n_edges + EB - 1) / EB;
    edge_kernel<<<nb, 128>>>(vec, ev, ed, erbf, Wrbf, brbf, eidx,
                             out_ds, out_dvec, n_edges, rcp);
}

// round 13
// speedup vs baseline: 1.1284x; 1.1284x over previous
#include <cuda_runtime.h>
#include <math.h>
#include <stdint.h>

// ---------------------------------------------------------------------------
// MessageBlock, round 13: warp-level tf32 mma.sync rbf filter (tcgen05 is
// unavailable: harness targets plain sm_103).
//   K0: node MLP -> g_phi, with fused zero of the output (R8-proven)
//   K1: edge kernel: per 24-edge block, mma.sync tf32 computes
//       a_sm[24 edge][384 ch] = rbf @ Wrbf^T; scatter loop is the exact
//       R2 (187us) loop with the 30-FMA2 dot replaced by 3 LDS.
// ---------------------------------------------------------------------------

#define F_DIM   128
#define PHI_DIM 384
#define RBF_D   20
#define TILE_M  32
#define KC      16
#define EB      24          // edges per block = MMA N (3 n-tiles of 8)
#define ASTRIDE 388         // a_sm row stride (floats); 388 % 32 = 4

typedef unsigned long long ull;

// static scratch (allowed)
__device__ float g_phi[10240 * PHI_DIM];   // 15.7 MB

__device__ __forceinline__ float decode_rc(const int* p) {
    int v = *p;
    if (v > 0 && v < 1000000) return (float)v;   // int32 scalar
    return __uint_as_float((unsigned)v);          // float32 scalar bits
}

// ---- packed f32x2 helpers (MLP) --------------------------------------------
__device__ __forceinline__ ull pk2(float lo, float hi) {
    ull r; asm("mov.b64 %0, {%1, %2};" : "=l"(r) : "f"(lo), "f"(hi)); return r;
}
__device__ __forceinline__ ull fma2(ull a, ull b, ull c) {
    ull d; asm("fma.rn.f32x2 %0, %1, %2, %3;" : "=l"(d) : "l"(a), "l"(b), "l"(c));
    return d;
}
__device__ __forceinline__ float2 unpk2(ull p) {
    float2 v; asm("mov.b64 {%0, %1}, %2;" : "=f"(v.x), "=f"(v.y) : "l"(p));
    return v;
}

// ---- tf32 mma.sync helpers --------------------------------------------------
__device__ __forceinline__ uint32_t to_tf32(float x) {
    uint32_t r; asm("cvt.rna.tf32.f32 %0, %1;" : "=r"(r) : "f"(x)); return r;
}
__device__ __forceinline__ void mma_tf32(float d[4], const uint32_t a[4],
                                         const uint32_t b[2]) {
    asm volatile(
        "mma.sync.aligned.m16n8k8.row.col.f32.tf32.tf32.f32 "
        "{%0,%1,%2,%3}, {%4,%5,%6,%7}, {%8,%9}, {%0,%1,%2,%3};\n"
        : "+f"(d[0]), "+f"(d[1]), "+f"(d[2]), "+f"(d[3])
        : "r"(a[0]), "r"(a[1]), "r"(a[2]), "r"(a[3]),
          "r"(b[0]), "r"(b[1]));
}

// ---------------------------------------------------------------------------
// K0: node MLP (exact R2 math) + fused zero of the poisoned output.
// ---------------------------------------------------------------------------
__global__ void __launch_bounds__(256) node_mlp_kernel(
    const float* __restrict__ s,
    const float* __restrict__ Ws1, const float* __restrict__ bs1,
    const float* __restrict__ Ws2, const float* __restrict__ bs2,
    int n_nodes,
    float* __restrict__ outp, int out_n)
{
    __shared__ __align__(16) float s_sm[TILE_M][F_DIM];
    __shared__ __align__(16) float h_sm[TILE_M][F_DIM];
    __shared__ __align__(16) float w_sm[KC][F_DIM + 4];

    const int tid   = threadIdx.x;
    const int m_blk = blockIdx.x * TILE_M;
    const int n0 = (tid & 31) * 4;
    const int m0 = (tid >> 5) * 4;

    // fused zero (grid-stride float4; out_n divisible by 4)
    {
        float4* o4 = (float4*)outp;
        const int n4 = out_n >> 2;
        const int gtid = blockIdx.x * 256 + tid;
        const int gsz  = gridDim.x * 256;
        for (int i = gtid; i < n4; i += gsz)
            o4[i] = make_float4(0.f, 0.f, 0.f, 0.f);
    }

    for (int i = tid; i < TILE_M * 32; i += 256) {
        int m = i >> 5;
        float4 v = make_float4(0.f, 0.f, 0.f, 0.f);
        if (m_blk + m < n_nodes)
            v = ((const float4*)s)[(size_t)(m_blk + m) * 32 + (i & 31)];
        ((float4*)s_sm)[i] = v;
    }

    ull accp[4][2];

    #pragma unroll
    for (int i = 0; i < 4; i++) { accp[i][0] = 0ull; accp[i][1] = 0ull; }

    for (int kc = 0; kc < F_DIM; kc += KC) {
        __syncthreads();
        for (int i = tid; i < KC * F_DIM; i += 256) {
            int kk = i & (KC - 1);
            int n  = i >> 4;
            w_sm[kk][n] = Ws1[n * F_DIM + kc + kk];
        }
        __syncthreads();
        #pragma unroll
        for (int k4 = 0; k4 < KC; k4 += 4) {
            float a[4][4];
            #pragma unroll
            for (int i = 0; i < 4; i++) {
                float4 t = *(const float4*)&s_sm[m0 + i][kc + k4];
                a[i][0] = t.x; a[i][1] = t.y; a[i][2] = t.z; a[i][3] = t.w;
            }
            #pragma unroll
            for (int kk = 0; kk < 4; kk++) {
                double2 bq = *(const double2*)&w_sm[k4 + kk][n0];
                ull bA = __double_as_longlong(bq.x);
                ull bB = __double_as_longlong(bq.y);
                #pragma unroll
                for (int i = 0; i < 4; i++) {
                    ull aa = pk2(a[i][kk], a[i][kk]);
                    accp[i][0] = fma2(aa, bA, accp[i][0]);
                    accp[i][1] = fma2(aa, bB, accp[i][1]);
                }
            }
        }
    }
    {
        float bb[4];
        #pragma unroll
        for (int j = 0; j < 4; j++) bb[j] = bs1[n0 + j];
        #pragma unroll
        for (int i = 0; i < 4; i++) {
            float2 e0 = unpk2(accp[i][0]);
            float2 e1 = unpk2(accp[i][1]);
            float4 hv; float x;
            x = e0.x + bb[0]; hv.x = x / (1.f + __expf(-x));
            x = e0.y + bb[1]; hv.y = x / (1.f + __expf(-x));
            x = e1.x + bb[2]; hv.z = x / (1.f + __expf(-x));
            x = e1.y + bb[3]; hv.w = x / (1.f + __expf(-x));
            *(float4*)&h_sm[m0 + i][n0] = hv;
        }
    }

    for (int p = 0; p < 3; p++) {
        #pragma unroll
        for (int i = 0; i < 4; i++) { accp[i][0] = 0ull; accp[i][1] = 0ull; }

        const float* W2 = Ws2 + (size_t)p * 128 * F_DIM;
        for (int kc = 0; kc < F_DIM; kc += KC) {
            __syncthreads();
            for (int i = tid; i < KC * F_DIM; i += 256) {
                int kk = i & (KC - 1);
                int n  = i >> 4;
                w_sm[kk][n] = W2[n * F_DIM + kc + kk];
            }
            __syncthreads();
            #pragma unroll
            for (int k4 = 0; k4 < KC; k4 += 4) {
                float a[4][4];
                #pragma unroll
                for (int i = 0; i < 4; i++) {
                    float4 t = *(const float4*)&h_sm[m0 + i][kc + k4];
                    a[i][0] = t.x; a[i][1] = t.y; a[i][2] = t.z; a[i][3] = t.w;
                }
                #pragma unroll
                for (int kk = 0; kk < 4; kk++) {
                    double2 bq = *(const double2*)&w_sm[k4 + kk][n0];
                    ull bA = __double_as_longlong(bq.x);
                    ull bB = __double_as_longlong(bq.y);
                    #pragma unroll
                    for (int i = 0; i < 4; i++) {
                        ull aa = pk2(a[i][kk], a[i][kk]);
                        accp[i][0] = fma2(aa, bA, accp[i][0]);
                        accp[i][1] = fma2(aa, bB, accp[i][1]);
                    }
                }
            }
        }
        float bb[4];
        #pragma unroll
        for (int j = 0; j < 4; j++) bb[j] = bs2[p * 128 + n0 + j];
        #pragma unroll
        for (int i = 0; i < 4; i++) {
            if (m_blk + m0 + i < n_nodes) {
                float2 e0 = unpk2(accp[i][0]);
                float2 e1 = unpk2(accp[i][1]);
                float4 ov = make_float4(e0.x + bb[0], e0.y + bb[1],
                                        e1.x + bb[2], e1.y + bb[3]);
                *(float4*)&g_phi[(size_t)(m_blk + m0 + i) * PHI_DIM + p * 128 + n0] = ov;
            }
        }
    }
}

// ---------------------------------------------------------------------------
// K1: edge kernel. 128 threads (4 warps), EB=24 edges.
// Phase 1: GEMM a_sm[e][ch] = rbf @ Wrbf^T via mma.sync tf32.
//   warp w owns m-tiles (channel 16-blocks) 6w..6w+5; 3 n-tiles of 8 edges;
//   K=20 padded to 24 (3 k-steps of 8). A from global Wrbf (L1-hot),
//   B from rbf_sm (tf32, [24 k][40] stride -> conflict-free).
// Phase 2: exact R2 scatter loop; per edge 3 LDS from a_sm replace the dot.
// Smem: rbf 3840B + a_sm 37248B + geo 384B + idx 192B = 41.7KB (static).
// ---------------------------------------------------------------------------
__global__ void __launch_bounds__(128) edge_kernel(
    const float* __restrict__ vec,
    const float* __restrict__ edge_vector,
    const float* __restrict__ edge_distance,
    const float* __restrict__ edge_rbf,
    const float* __restrict__ Wrbf, const float* __restrict__ brbf,
    const int*   __restrict__ edge_idx,
    float* __restrict__ out_ds, float* __restrict__ out_dvec,
    int n_edges, const int* __restrict__ cutoff_ptr)
{
    __shared__ __align__(16) float rbf_sm[24 * 40];        // B, tf32 bits
    __shared__ __align__(16) float a_sm[EB * ASTRIDE];     // D: [edge][ch]
    __shared__ float4 geo_sm[EB];
    __shared__ int2   idx_sm[EB];

    const int tid  = threadIdx.x;
    const int wid  = tid >> 5;
    const int lane = tid & 31;
    const float rc     = decode_rc(cutoff_ptr);
    const float inv_rc = 1.0f / rc;

    const int e0  = blockIdx.x * EB;
    const int cnt = min(EB, n_edges - e0);

    // ---- stage B (rbf) as tf32, layout [k][edge] stride 40, zero-padded ----
    for (int i = tid; i < 24 * EB; i += 128) {
        const int e = i / 24;
        const int k = i - e * 24;
        float v = (e < cnt && k < RBF_D)
                  ? edge_rbf[(size_t)(e0 + e) * RBF_D + k] : 0.f;
        rbf_sm[k * 40 + e] = __uint_as_float(to_tf32(v));
    }
    // ---- stage geo/idx ----
    if (tid < cnt) {
        const int e = e0 + tid;
        const float d = edge_distance[e];
        float fc = 0.5f * (cospif(d * inv_rc) + 1.0f);
        fc = (d < rc) ? fc : 0.0f;
        const float inv_d = 1.0f / d;
        geo_sm[tid] = make_float4(edge_vector[e * 3 + 0] * inv_d,
                                  edge_vector[e * 3 + 1] * inv_d,
                                  edge_vector[e * 3 + 2] * inv_d,
                                  fc);
        idx_sm[tid] = make_int2(edge_idx[e],              // dst (receiver)
                                edge_idx[n_edges + e]);   // src (sender)
    }
    __syncthreads();

    // ---- Phase 1: GEMM via mma.sync ----
    {
        const int gr = lane >> 2;     // 0..7  (M row group / N col)
        const int gc = lane & 3;      // 0..3  (K col group)
        #pragma unroll 1
        for (int mi = 0; mi < 6; mi++) {
            const int chb = (wid * 6 + mi) * 16;   // channel base (row of Wrbf)
            // A fragments for 3 k-steps (from global; Wrbf is L1-hot)
            uint32_t afr[3][4];
            #pragma unroll
            for (int ks = 0; ks < 3; ks++) {
                const int kb = ks * 8;
                const int r0 = chb + gr, r1 = r0 + 8;
                const int c0 = kb + gc,  c1 = c0 + 4;
                afr[ks][0] = (c0 < RBF_D) ? to_tf32(Wrbf[r0 * RBF_D + c0]) : 0u;
                afr[ks][1] = (c0 < RBF_D) ? to_tf32(Wrbf[r1 * RBF_D + c0]) : 0u;
                afr[ks][2] = (c1 < RBF_D) ? to_tf32(Wrbf[r0 * RBF_D + c1]) : 0u;
                afr[ks][3] = (c1 < RBF_D) ? to_tf32(Wrbf[r1 * RBF_D + c1]) : 0u;
            }
            #pragma unroll
            for (int nb = 0; nb < EB; nb += 8) {
                uint32_t bfr[3][2];
                #pragma unroll
                for (int ks = 0; ks < 3; ks++) {
                    bfr[ks][0] = __float_as_uint(rbf_sm[(ks * 8 + gc)     * 40 + nb + gr]);
                    bfr[ks][1] = __float_as_uint(rbf_sm[(ks * 8 + gc + 4) * 40 + nb + gr]);
                }
                float d[4] = {0.f, 0.f, 0.f, 0.f};
                #pragma unroll
                for (int ks = 0; ks < 3; ks++) mma_tf32(d, afr[ks], bfr[ks]);
                // D mapping: row(ch) = gr (+8), col(edge) = 2*gc (+1)
                const int ea = nb + 2 * gc;
                a_sm[(ea    ) * ASTRIDE + chb + gr    ] = d[0];
                a_sm[(ea + 1) * ASTRIDE + chb + gr    ] = d[1];
                a_sm[(ea    ) * ASTRIDE + chb + gr + 8] = d[2];
                a_sm[(ea + 1) * ASTRIDE + chb + gr + 8] = d[3];
            }
        }
    }
    __syncthreads();

    // ---- Phase 2: scatter (exact R2 loop, dot replaced by 3 LDS) ----
    const float b0 = brbf[tid], b1 = brbf[tid + 128], b2 = brbf[tid + 256];

    #pragma unroll 2
    for (int el = 0; el < cnt; el++) {
        const int2   ii = idx_sm[el];
        const float4 g  = geo_sm[el];
        const int dst = ii.x, src = ii.y;
        const float fc = g.w;

        const float* ap = a_sm + el * ASTRIDE;
        const float a0 = (ap[tid]       + b0) * fc;
        const float a1 = (ap[tid + 128] + b1) * fc;
        const float a2 = (ap[tid + 256] + b2) * fc;

        const float* ph = g_phi + (size_t)src * PHI_DIM;
        const float ws  = __ldg(ph + tid)       * a0;
        const float wvv = __ldg(ph + tid + 128) * a1;
        const float wvs = __ldg(ph + tid + 256) * a2;

        atomicAdd(out_ds + (size_t)dst * F_DIM + tid, ws);

        const float* vp = vec + (size_t)src * PHI_DIM;
        float* op = out_dvec + (size_t)dst * PHI_DIM + tid;
        atomicAdd(op,       fmaf(wvv, __ldg(vp + tid      ), g.x * wvs));
        atomicAdd(op + 128, fmaf(wvv, __ldg(vp + tid + 128), g.y * wvs));
        atomicAdd(op + 256, fmaf(wvv, __ldg(vp + tid + 256), g.z * wvs));
    }
}

// ---------------------------------------------------------------------------
extern "C" void kernel_launch(void* const* d_in, const int* in_sizes, int n_in,
                              void* d_out, int out_size) {
    const float* s    = (const float*)d_in[0];
    const float* vec  = (const float*)d_in[1];
    const float* ev   = (const float*)d_in[2];
    const float* ed   = (const float*)d_in[3];
    const float* erbf = (const float*)d_in[4];
    const float* Ws1  = (const float*)d_in[5];
    const float* bs1  = (const float*)d_in[6];
    const float* Ws2  = (const float*)d_in[7];
    const float* bs2  = (const float*)d_in[8];
    const float* Wrbf = (const float*)d_in[9];
    const float* brbf = (const float*)d_in[10];
    const int*   eidx = (const int*)d_in[11];
    const int*   rcp  = (const int*)d_in[12];

    const int n_nodes = in_sizes[0] / F_DIM;
    const int n_edges = in_sizes[3];
    float* out_ds   = (float*)d_out;
    float* out_dvec = out_ds + (size_t)n_nodes * F_DIM;

    // K0: fused zero + per-node MLP -> g_phi
    node_mlp_kernel<<<(n_nodes + TILE_M - 1) / TILE_M, 256>>>(
        s, Ws1, bs1, Ws2, bs2, n_nodes, (float*)d_out, out_size);

    // K1: edge kernel (mma.sync filter + R2 scatter)
    int nb = (n_edges + EB - 1) / EB;
    edge_kernel<<<nb, 128>>>(vec, ev, ed, erbf, Wrbf, brbf, eidx,
                             out_ds, out_dvec, n_edges, rcp);
}

// round 14
// speedup vs baseline: 1.2046x; 1.0675x over previous
#include <cuda_runtime.h>
#include <cuda_bf16.h>
#include <math.h>

// ---------------------------------------------------------------------------
// MessageBlock, round 14: composition of measured-best components.
//   K0: fused zero + node MLP  (51.1us measured in R13)
//   K1: edge kernel, exact R2/R11 version (128.3us measured in R11)
// Predicted total ~178-182us vs 187.1 best.
// ---------------------------------------------------------------------------

#define F_DIM   128
#define PHI_DIM 384
#define RBF_D   20
#define TILE_M  32
#define KC      16
#define EB      64   // edges per block

typedef unsigned long long ull;

// scratch for per-node phi (15.7 MB), static device allocation (allowed)
__device__ float g_phi[10240 * PHI_DIM];

__device__ __forceinline__ float decode_rc(const int* p) {
    int v = *p;
    if (v > 0 && v < 1000000) return (float)v;   // int32 scalar
    return __uint_as_float((unsigned)v);          // float32 scalar bits
}

// ---- packed f32x2 helpers (sm_103a FFMA2 path) -----------------------------
__device__ __forceinline__ ull pk2(float lo, float hi) {
    ull r; asm("mov.b64 %0, {%1, %2};" : "=l"(r) : "f"(lo), "f"(hi)); return r;
}
__device__ __forceinline__ ull fma2(ull a, ull b, ull c) {
    ull d; asm("fma.rn.f32x2 %0, %1, %2, %3;" : "=l"(d) : "l"(a), "l"(b), "l"(c));
    return d;
}
__device__ __forceinline__ float2 unpk2(ull p) {
    float2 v; asm("mov.b64 {%0, %1}, %2;" : "=f"(v.x), "=f"(v.y) : "l"(p));
    return v;
}

// ---------------------------------------------------------------------------
// K0: node MLP (exact R2 math) + fused zero of the poisoned output.
// ---------------------------------------------------------------------------
__global__ void __launch_bounds__(256) node_mlp_kernel(
    const float* __restrict__ s,
    const float* __restrict__ Ws1, const float* __restrict__ bs1,
    const float* __restrict__ Ws2, const float* __restrict__ bs2,
    int n_nodes,
    float* __restrict__ outp, int out_n)
{
    __shared__ __align__(16) float s_sm[TILE_M][F_DIM];
    __shared__ __align__(16) float h_sm[TILE_M][F_DIM];
    __shared__ __align__(16) float w_sm[KC][F_DIM + 4];

    const int tid   = threadIdx.x;
    const int m_blk = blockIdx.x * TILE_M;
    const int n0 = (tid & 31) * 4;
    const int m0 = (tid >> 5) * 4;

    // fused zero (grid-stride float4; out_n divisible by 4)
    {
        float4* o4 = (float4*)outp;
        const int n4 = out_n >> 2;
        const int gtid = blockIdx.x * 256 + tid;
        const int gsz  = gridDim.x * 256;
        for (int i = gtid; i < n4; i += gsz)
            o4[i] = make_float4(0.f, 0.f, 0.f, 0.f);
    }

    for (int i = tid; i < TILE_M * 32; i += 256) {
        int m = i >> 5;
        float4 v = make_float4(0.f, 0.f, 0.f, 0.f);
        if (m_blk + m < n_nodes)
            v = ((const float4*)s)[(size_t)(m_blk + m) * 32 + (i & 31)];
        ((float4*)s_sm)[i] = v;
    }

    ull accp[4][2];

    #pragma unroll
    for (int i = 0; i < 4; i++) { accp[i][0] = 0ull; accp[i][1] = 0ull; }

    for (int kc = 0; kc < F_DIM; kc += KC) {
        __syncthreads();
        for (int i = tid; i < KC * F_DIM; i += 256) {
            int kk = i & (KC - 1);
            int n  = i >> 4;
            w_sm[kk][n] = Ws1[n * F_DIM + kc + kk];
        }
        __syncthreads();
        #pragma unroll
        for (int k4 = 0; k4 < KC; k4 += 4) {
            float a[4][4];
            #pragma unroll
            for (int i = 0; i < 4; i++) {
                float4 t = *(const float4*)&s_sm[m0 + i][kc + k4];
                a[i][0] = t.x; a[i][1] = t.y; a[i][2] = t.z; a[i][3] = t.w;
            }
            #pragma unroll
            for (int kk = 0; kk < 4; kk++) {
                double2 bq = *(const double2*)&w_sm[k4 + kk][n0];
                ull bA = __double_as_longlong(bq.x);
                ull bB = __double_as_longlong(bq.y);
                #pragma unroll
                for (int i = 0; i < 4; i++) {
                    ull aa = pk2(a[i][kk], a[i][kk]);
                    accp[i][0] = fma2(aa, bA, accp[i][0]);
                    accp[i][1] = fma2(aa, bB, accp[i][1]);
                }
            }
        }
    }
    {
        float bb[4];
        #pragma unroll
        for (int j = 0; j < 4; j++) bb[j] = bs1[n0 + j];
        #pragma unroll
        for (int i = 0; i < 4; i++) {
            float2 e0 = unpk2(accp[i][0]);
            float2 e1 = unpk2(accp[i][1]);
            float4 hv; float x;
            x = e0.x + bb[0]; hv.x = x / (1.f + __expf(-x));
            x = e0.y + bb[1]; hv.y = x / (1.f + __expf(-x));
            x = e1.x + bb[2]; hv.z = x / (1.f + __expf(-x));
            x = e1.y + bb[3]; hv.w = x / (1.f + __expf(-x));
            *(float4*)&h_sm[m0 + i][n0] = hv;
        }
    }

    for (int p = 0; p < 3; p++) {
        #pragma unroll
        for (int i = 0; i < 4; i++) { accp[i][0] = 0ull; accp[i][1] = 0ull; }

        const float* W2 = Ws2 + (size_t)p * 128 * F_DIM;
        for (int kc = 0; kc < F_DIM; kc += KC) {
            __syncthreads();
            for (int i = tid; i < KC * F_DIM; i += 256) {
                int kk = i & (KC - 1);
                int n  = i >> 4;
                w_sm[kk][n] = W2[n * F_DIM + kc + kk];
            }
            __syncthreads();
            #pragma unroll
            for (int k4 = 0; k4 < KC; k4 += 4) {
                float a[4][4];
                #pragma unroll
                for (int i = 0; i < 4; i++) {
                    float4 t = *(const float4*)&h_sm[m0 + i][kc + k4];
                    a[i][0] = t.x; a[i][1] = t.y; a[i][2] = t.z; a[i][3] = t.w;
                }
                #pragma unroll
                for (int kk = 0; kk < 4; kk++) {
                    double2 bq = *(const double2*)&w_sm[k4 + kk][n0];
                    ull bA = __double_as_longlong(bq.x);
                    ull bB = __double_as_longlong(bq.y);
                    #pragma unroll
                    for (int i = 0; i < 4; i++) {
                        ull aa = pk2(a[i][kk], a[i][kk]);
                        accp[i][0] = fma2(aa, bA, accp[i][0]);
                        accp[i][1] = fma2(aa, bB, accp[i][1]);
                    }
                }
            }
        }
        float bb[4];
        #pragma unroll
        for (int j = 0; j < 4; j++) bb[j] = bs2[p * 128 + n0 + j];
        #pragma unroll
        for (int i = 0; i < 4; i++) {
            if (m_blk + m0 + i < n_nodes) {
                float2 e0 = unpk2(accp[i][0]);
                float2 e1 = unpk2(accp[i][1]);
                float4 ov = make_float4(e0.x + bb[0], e0.y + bb[1],
                                        e1.x + bb[2], e1.y + bb[3]);
                *(float4*)&g_phi[(size_t)(m_blk + m0 + i) * PHI_DIM + p * 128 + n0] = ov;
            }
        }
    }
}

// ---------------------------------------------------------------------------
// K1: edge kernel — EXACT R2/R11 version (measured 128.3us standalone).
// 128 threads, thread t owns feature channels {t, t+128, t+256}.
// ---------------------------------------------------------------------------
__global__ void __launch_bounds__(128) edge_kernel(
    const float* __restrict__ vec,
    const float* __restrict__ edge_vector,
    const float* __restrict__ edge_distance,
    const float* __restrict__ edge_rbf,
    const float* __restrict__ Wrbf, const float* __restrict__ brbf,
    const int*   __restrict__ edge_idx,
    float* __restrict__ out_ds, float* __restrict__ out_dvec,
    int n_edges, const int* __restrict__ cutoff_ptr)
{
    __shared__ __align__(16) float rbf_sm[EB * RBF_D];   // 5 KB
    __shared__ float4 geo_sm[EB];                        // vn0,vn1,vn2,fcut
    __shared__ int2   idx_sm[EB];                        // (dst, src)

    const int tid = threadIdx.x;
    const float rc     = decode_rc(cutoff_ptr);
    const float inv_rc = 1.0f / rc;

    ull wp0[RBF_D / 2], wp1[RBF_D / 2], wp2[RBF_D / 2];
    #pragma unroll
    for (int q = 0; q < RBF_D / 2; q++) {
        wp0[q] = pk2(Wrbf[(tid      ) * RBF_D + 2 * q], Wrbf[(tid      ) * RBF_D + 2 * q + 1]);
        wp1[q] = pk2(Wrbf[(tid + 128) * RBF_D + 2 * q], Wrbf[(tid + 128) * RBF_D + 2 * q + 1]);
        wp2[q] = pk2(Wrbf[(tid + 256) * RBF_D + 2 * q], Wrbf[(tid + 256) * RBF_D + 2 * q + 1]);
    }
    const float b0 = brbf[tid], b1 = brbf[tid + 128], b2 = brbf[tid + 256];

    const int n_batches = (n_edges + EB - 1) / EB;
    for (int batch = blockIdx.x; batch < n_batches; batch += gridDim.x) {
        const int e0  = batch * EB;
        const int cnt = min(EB, n_edges - e0);

        __syncthreads();
        {
            const float4* src4 = (const float4*)(edge_rbf + (size_t)e0 * RBF_D);
            float4* dst4 = (float4*)rbf_sm;
            const int n4 = cnt * (RBF_D / 4);
            for (int i = tid; i < n4; i += 128) dst4[i] = src4[i];
        }
        if (tid < cnt) {
            const int e = e0 + tid;
            const float d = edge_distance[e];
            float fc = 0.5f * (cospif(d * inv_rc) + 1.0f);
            fc = (d < rc) ? fc : 0.0f;
            const float inv_d = 1.0f / d;
            geo_sm[tid] = make_float4(edge_vector[e * 3 + 0] * inv_d,
                                      edge_vector[e * 3 + 1] * inv_d,
                                      edge_vector[e * 3 + 2] * inv_d,
                                      fc);
            idx_sm[tid] = make_int2(edge_idx[e],              // dst (receiver)
                                    edge_idx[n_edges + e]);   // src (sender)
        }
        __syncthreads();

        #pragma unroll 1
        for (int el = 0; el < cnt; el++) {
            const int2  ii = idx_sm[el];
            const float4 g = geo_sm[el];
            const int dst = ii.x, src = ii.y;

            const double2* fp = (const double2*)(rbf_sm + el * RBF_D);
            ull acc0 = 0ull, acc1 = 0ull, acc2 = 0ull;
            #pragma unroll
            for (int q = 0; q < 5; q++) {
                double2 f = fp[q];
                ull fA = __double_as_longlong(f.x);
                ull fB = __double_as_longlong(f.y);
                acc0 = fma2(fA, wp0[2 * q], acc0);
                acc1 = fma2(fA, wp1[2 * q], acc1);
                acc2 = fma2(fA, wp2[2 * q], acc2);
                acc0 = fma2(fB, wp0[2 * q + 1], acc0);
                acc1 = fma2(fB, wp1[2 * q + 1], acc1);
                acc2 = fma2(fB, wp2[2 * q + 1], acc2);
            }
            float2 u0 = unpk2(acc0), u1 = unpk2(acc1), u2 = unpk2(acc2);
            const float fc = g.w;
            const float a0 = (u0.x + u0.y + b0) * fc;
            const float a1 = (u1.x + u1.y + b1) * fc;
            const float a2 = (u2.x + u2.y + b2) * fc;

            const float* ph = g_phi + (size_t)src * PHI_DIM;
            const float ws  = __ldg(ph + tid)       * a0;
            const float wvv = __ldg(ph + tid + 128) * a1;
            const float wvs = __ldg(ph + tid + 256) * a2;

            atomicAdd(out_ds + (size_t)dst * F_DIM + tid, ws);

            const float* vp = vec + (size_t)src * PHI_DIM;
            float* op = out_dvec + (size_t)dst * PHI_DIM + tid;
            atomicAdd(op,       fmaf(wvv, __ldg(vp + tid      ), g.x * wvs));
            atomicAdd(op + 128, fmaf(wvv, __ldg(vp + tid + 128), g.y * wvs));
            atomicAdd(op + 256, fmaf(wvv, __ldg(vp + tid + 256), g.z * wvs));
        }
    }
}

// ---------------------------------------------------------------------------
extern "C" void kernel_launch(void* const* d_in, const int* in_sizes, int n_in,
                              void* d_out, int out_size) {
    const float* s    = (const float*)d_in[0];
    const float* vec  = (const float*)d_in[1];
    const float* ev   = (const float*)d_in[2];
    const float* ed   = (const float*)d_in[3];
    const float* erbf = (const float*)d_in[4];
    const float* Ws1  = (const float*)d_in[5];
    const float* bs1  = (const float*)d_in[6];
    const float* Ws2  = (const float*)d_in[7];
    const float* bs2  = (const float*)d_in[8];
    const float* Wrbf = (const float*)d_in[9];
    const float* brbf = (const float*)d_in[10];
    const int*   eidx = (const int*)d_in[11];
    const int*   rcp  = (const int*)d_in[12];

    const int n_nodes = in_sizes[0] / F_DIM;
    const int n_edges = in_sizes[3];
    float* out_ds   = (float*)d_out;
    float* out_dvec = out_ds + (size_t)n_nodes * F_DIM;

    // K0: fused zero + per-node MLP -> g_phi
    node_mlp_kernel<<<(n_nodes + TILE_M - 1) / TILE_M, 256>>>(
        s, Ws1, bs1, Ws2, bs2, n_nodes, (float*)d_out, out_size);

    // K1: per-edge filter + scatter (exact R2/R11 version)
    int nb = (n_edges + EB - 1) / EB;
    edge_kernel<<<nb, 128>>>(vec, ev, ed, erbf, Wrbf, brbf, eidx,
                             out_ds, out_dvec, n_edges, rcp);
}

// round 15
// speedup vs baseline: 1.2318x; 1.0226x over previous
#include <cuda_runtime.h>
#include <cuda_bf16.h>
#include <math.h>

// ---------------------------------------------------------------------------
// MessageBlock, round 15:
//   K0: fused zero + node MLP with DOUBLE-BUFFERED register-staged weight
//       pipeline (weight LDG latency off the critical path; was 32x ~300cyc
//       serial per block). s-buffer reused for h (smem 33KB).
//   K1: edge kernel, exact R2/R11/R14 version (128.3us measured, stable).
// ---------------------------------------------------------------------------

#define F_DIM   128
#define PHI_DIM 384
#define RBF_D   20
#define TILE_M  32
#define KC      16
#define EB      64   // edges per block

typedef unsigned long long ull;

// scratch for per-node phi (15.7 MB), static device allocation (allowed)
__device__ float g_phi[10240 * PHI_DIM];

__device__ __forceinline__ float decode_rc(const int* p) {
    int v = *p;
    if (v > 0 && v < 1000000) return (float)v;   // int32 scalar
    return __uint_as_float((unsigned)v);          // float32 scalar bits
}

// ---- packed f32x2 helpers (sm_103a FFMA2 path) -----------------------------
__device__ __forceinline__ ull pk2(float lo, float hi) {
    ull r; asm("mov.b64 %0, {%1, %2};" : "=l"(r) : "f"(lo), "f"(hi)); return r;
}
__device__ __forceinline__ ull fma2(ull a, ull b, ull c) {
    ull d; asm("fma.rn.f32x2 %0, %1, %2, %3;" : "=l"(d) : "l"(a), "l"(b), "l"(c));
    return d;
}
__device__ __forceinline__ float2 unpk2(ull p) {
    float2 v; asm("mov.b64 {%0, %1}, %2;" : "=f"(v.x), "=f"(v.y) : "l"(p));
    return v;
}

// ---------------------------------------------------------------------------
// K0: fused zero + node MLP with pipelined weight staging.
// phi = (silu(s @ Ws1^T + bs1)) @ Ws2^T + bs2 -> g_phi [N,384]
// 32 chunks of 16 k: chunks 0-7 = stage1 (Ws1), 8-31 = stage2 passes 0-2.
// ---------------------------------------------------------------------------
__global__ void __launch_bounds__(256) node_mlp_kernel(
    const float* __restrict__ s,
    const float* __restrict__ Ws1, const float* __restrict__ bs1,
    const float* __restrict__ Ws2, const float* __restrict__ bs2,
    int n_nodes,
    float* __restrict__ outp, int out_n)
{
    __shared__ __align__(16) float sh_sm[TILE_M][F_DIM];        // s, then h
    __shared__ __align__(16) float w_sm[2][KC][F_DIM + 4];      // double buffer

    const int tid   = threadIdx.x;
    const int m_blk = blockIdx.x * TILE_M;
    const int n0 = (tid & 31) * 4;
    const int m0 = (tid >> 5) * 4;

    // fused zero of the poisoned output (grid-stride float4)
    {
        float4* o4 = (float4*)outp;
        const int n4 = out_n >> 2;
        const int gtid = blockIdx.x * 256 + tid;
        const int gsz  = gridDim.x * 256;
        for (int i = gtid; i < n4; i += gsz)
            o4[i] = make_float4(0.f, 0.f, 0.f, 0.f);
    }

    // stage s tile (zero-pad past n_nodes)
    for (int i = tid; i < TILE_M * 32; i += 256) {
        int m = i >> 5;
        float4 v = make_float4(0.f, 0.f, 0.f, 0.f);
        if (m_blk + m < n_nodes)
            v = ((const float4*)s)[(size_t)(m_blk + m) * 32 + (i & 31)];
        ((float4*)sh_sm)[i] = v;
    }

    // per-thread weight indices: i = tid + j*256, kk = i&15, n = i>>4
    const int w_kk[2] = { tid & 15, (tid + 256) & 15 };   // pattern repeats mod 2
    // (tid + j*256): kk = tid&15 for all j (256 % 16 == 0); n = (tid>>4) + j*16
    const int kk0 = tid & 15;
    const int nn0 = tid >> 4;
    (void)w_kk;

    float wreg[8];
    // prefetch chunk 0 (Ws1, kbase 0)
    #pragma unroll
    for (int j = 0; j < 8; j++)
        wreg[j] = __ldg(Ws1 + (nn0 + j * 16) * F_DIM + kk0);

    ull accp[4][2];
    #pragma unroll
    for (int i = 0; i < 4; i++) { accp[i][0] = 0ull; accp[i][1] = 0ull; }

    #pragma unroll 1
    for (int c = 0; c < 32; c++) {
        const int buf = c & 1;
        // STS current chunk
        #pragma unroll
        for (int j = 0; j < 8; j++)
            w_sm[buf][kk0][nn0 + j * 16] = wreg[j];
        __syncthreads();

        // prefetch next chunk
        if (c < 31) {
            const int cn = c + 1;
            const float* W;
            int kbase;
            if (cn < 8) { W = Ws1; kbase = cn * 16; }
            else {
                W = Ws2 + (size_t)((cn - 8) >> 3) * 128 * F_DIM;
                kbase = (cn & 7) * 16;
            }
            #pragma unroll
            for (int j = 0; j < 8; j++)
                wreg[j] = __ldg(W + (nn0 + j * 16) * F_DIM + kbase + kk0);
        }

        // compute chunk c
        const int kc = (c & 7) * 16;
        #pragma unroll
        for (int k4 = 0; k4 < KC; k4 += 4) {
            float a[4][4];
            #pragma unroll
            for (int i = 0; i < 4; i++) {
                float4 t = *(const float4*)&sh_sm[m0 + i][kc + k4];
                a[i][0] = t.x; a[i][1] = t.y; a[i][2] = t.z; a[i][3] = t.w;
            }
            #pragma unroll
            for (int kk = 0; kk < 4; kk++) {
                double2 bq = *(const double2*)&w_sm[buf][k4 + kk][n0];
                ull bA = __double_as_longlong(bq.x);
                ull bB = __double_as_longlong(bq.y);
                #pragma unroll
                for (int i = 0; i < 4; i++) {
                    ull aa = pk2(a[i][kk], a[i][kk]);
                    accp[i][0] = fma2(aa, bA, accp[i][0]);
                    accp[i][1] = fma2(aa, bB, accp[i][1]);
                }
            }
        }

        // pass boundaries
        if (c == 7) {
            // stage 1 done: silu + bias -> h overwrites sh_sm
            __syncthreads();   // all warps finished reading s
            float bb[4];
            #pragma unroll
            for (int j = 0; j < 4; j++) bb[j] = bs1[n0 + j];
            #pragma unroll
            for (int i = 0; i < 4; i++) {
                float2 e0 = unpk2(accp[i][0]);
                float2 e1 = unpk2(accp[i][1]);
                float4 hv; float x;
                x = e0.x + bb[0]; hv.x = x / (1.f + __expf(-x));
                x = e0.y + bb[1]; hv.y = x / (1.f + __expf(-x));
                x = e1.x + bb[2]; hv.z = x / (1.f + __expf(-x));
                x = e1.y + bb[3]; hv.w = x / (1.f + __expf(-x));
                *(float4*)&sh_sm[m0 + i][n0] = hv;
                accp[i][0] = 0ull; accp[i][1] = 0ull;
            }
            // visibility of h: covered by the sync at top of chunk 8
        } else if (c > 7 && (c & 7) == 7) {
            // stage-2 pass p complete: write g_phi
            const int p = (c - 8) >> 3;
            float bb[4];
            #pragma unroll
            for (int j = 0; j < 4; j++) bb[j] = bs2[p * 128 + n0 + j];
            #pragma unroll
            for (int i = 0; i < 4; i++) {
                if (m_blk + m0 + i < n_nodes) {
                    float2 e0 = unpk2(accp[i][0]);
                    float2 e1 = unpk2(accp[i][1]);
                    float4 ov = make_float4(e0.x + bb[0], e0.y + bb[1],
                                            e1.x + bb[2], e1.y + bb[3]);
                    *(float4*)&g_phi[(size_t)(m_blk + m0 + i) * PHI_DIM + p * 128 + n0] = ov;
                }
                accp[i][0] = 0ull; accp[i][1] = 0ull;
            }
        }
    }
}

// ---------------------------------------------------------------------------
// K1: edge kernel — EXACT R2/R11/R14 version (measured 128.3us standalone).
// 128 threads, thread t owns feature channels {t, t+128, t+256}.
// ---------------------------------------------------------------------------
__global__ void __launch_bounds__(128) edge_kernel(
    const float* __restrict__ vec,
    const float* __restrict__ edge_vector,
    const float* __restrict__ edge_distance,
    const float* __restrict__ edge_rbf,
    const float* __restrict__ Wrbf, const float* __restrict__ brbf,
    const int*   __restrict__ edge_idx,
    float* __restrict__ out_ds, float* __restrict__ out_dvec,
    int n_edges, const int* __restrict__ cutoff_ptr)
{
    __shared__ __align__(16) float rbf_sm[EB * RBF_D];   // 5 KB
    __shared__ float4 geo_sm[EB];                        // vn0,vn1,vn2,fcut
    __shared__ int2   idx_sm[EB];                        // (dst, src)

    const int tid = threadIdx.x;
    const float rc     = decode_rc(cutoff_ptr);
    const float inv_rc = 1.0f / rc;

    ull wp0[RBF_D / 2], wp1[RBF_D / 2], wp2[RBF_D / 2];
    #pragma unroll
    for (int q = 0; q < RBF_D / 2; q++) {
        wp0[q] = pk2(Wrbf[(tid      ) * RBF_D + 2 * q], Wrbf[(tid      ) * RBF_D + 2 * q + 1]);
        wp1[q] = pk2(Wrbf[(tid + 128) * RBF_D + 2 * q], Wrbf[(tid + 128) * RBF_D + 2 * q + 1]);
        wp2[q] = pk2(Wrbf[(tid + 256) * RBF_D + 2 * q], Wrbf[(tid + 256) * RBF_D + 2 * q + 1]);
    }
    const float b0 = brbf[tid], b1 = brbf[tid + 128], b2 = brbf[tid + 256];

    const int n_batches = (n_edges + EB - 1) / EB;
    for (int batch = blockIdx.x; batch < n_batches; batch += gridDim.x) {
        const int e0  = batch * EB;
        const int cnt = min(EB, n_edges - e0);

        __syncthreads();
        {
            const float4* src4 = (const float4*)(edge_rbf + (size_t)e0 * RBF_D);
            float4* dst4 = (float4*)rbf_sm;
            const int n4 = cnt * (RBF_D / 4);
            for (int i = tid; i < n4; i += 128) dst4[i] = src4[i];
        }
        if (tid < cnt) {
            const int e = e0 + tid;
            const float d = edge_distance[e];
            float fc = 0.5f * (cospif(d * inv_rc) + 1.0f);
            fc = (d < rc) ? fc : 0.0f;
            const float inv_d = 1.0f / d;
            geo_sm[tid] = make_float4(edge_vector[e * 3 + 0] * inv_d,
                                      edge_vector[e * 3 + 1] * inv_d,
                                      edge_vector[e * 3 + 2] * inv_d,
                                      fc);
            idx_sm[tid] = make_int2(edge_idx[e],              // dst (receiver)
                                    edge_idx[n_edges + e]);   // src (sender)
        }
        __syncthreads();

        #pragma unroll 1
        for (int el = 0; el < cnt; el++) {
            const int2  ii = idx_sm[el];
            const float4 g = geo_sm[el];
            const int dst = ii.x, src = ii.y;

            const double2* fp = (const double2*)(rbf_sm + el * RBF_D);
            ull acc0 = 0ull, acc1 = 0ull, acc2 = 0ull;
            #pragma unroll
            for (int q = 0; q < 5; q++) {
                double2 f = fp[q];
                ull fA = __double_as_longlong(f.x);
                ull fB = __double_as_longlong(f.y);
                acc0 = fma2(fA, wp0[2 * q], acc0);
                acc1 = fma2(fA, wp1[2 * q], acc1);
                acc2 = fma2(fA, wp2[2 * q], acc2);
                acc0 = fma2(fB, wp0[2 * q + 1], acc0);
                acc1 = fma2(fB, wp1[2 * q + 1], acc1);
                acc2 = fma2(fB, wp2[2 * q + 1], acc2);
            }
            float2 u0 = unpk2(acc0), u1 = unpk2(acc1), u2 = unpk2(acc2);
            const float fc = g.w;
            const float a0 = (u0.x + u0.y + b0) * fc;
            const float a1 = (u1.x + u1.y + b1) * fc;
            const float a2 = (u2.x + u2.y + b2) * fc;

            const float* ph = g_phi + (size_t)src * PHI_DIM;
            const float ws  = __ldg(ph + tid)       * a0;
            const float wvv = __ldg(ph + tid + 128) * a1;
            const float wvs = __ldg(ph + tid + 256) * a2;

            atomicAdd(out_ds + (size_t)dst * F_DIM + tid, ws);

            const float* vp = vec + (size_t)src * PHI_DIM;
            float* op = out_dvec + (size_t)dst * PHI_DIM + tid;
            atomicAdd(op,       fmaf(wvv, __ldg(vp + tid      ), g.x * wvs));
            atomicAdd(op + 128, fmaf(wvv, __ldg(vp + tid + 128), g.y * wvs));
            atomicAdd(op + 256, fmaf(wvv, __ldg(vp + tid + 256), g.z * wvs));
        }
    }
}

// ---------------------------------------------------------------------------
extern "C" void kernel_launch(void* const* d_in, const int* in_sizes, int n_in,
                              void* d_out, int out_size) {
    const float* s    = (const float*)d_in[0];
    const float* vec  = (const float*)d_in[1];
    const float* ev   = (const float*)d_in[2];
    const float* ed   = (const float*)d_in[3];
    const float* erbf = (const float*)d_in[4];
    const float* Ws1  = (const float*)d_in[5];
    const float* bs1  = (const float*)d_in[6];
    const float* Ws2  = (const float*)d_in[7];
    const float* bs2  = (const float*)d_in[8];
    const float* Wrbf = (const float*)d_in[9];
    const float* brbf = (const float*)d_in[10];
    const int*   eidx = (const int*)d_in[11];
    const int*   rcp  = (const int*)d_in[12];

    const int n_nodes = in_sizes[0] / F_DIM;
    const int n_edges = in_sizes[3];
    float* out_ds   = (float*)d_out;
    float* out_dvec = out_ds + (size_t)n_nodes * F_DIM;

    // K0: fused zero + pipelined per-node MLP -> g_phi
    node_mlp_kernel<<<(n_nodes + TILE_M - 1) / TILE_M, 256>>>(
        s, Ws1, bs1, Ws2, bs2, n_nodes, (float*)d_out, out_size);

    // K1: per-edge filter + scatter (exact R2/R11/R14 version)
    int nb = (n_edges + EB - 1) / EB;
    edge_kernel<<<nb, 128>>>(vec, ev, ed, erbf, Wrbf, brbf, eidx,
                             out_ds, out_dvec, n_edges, rcp);
}